// round 16
// baseline (speedup 1.0000x reference)
#include <cuda_runtime.h>
#include <cstdint>

#define BB 4
#define SS 2048
#define DD 512
#define HH 8
#define DKK 64
#define MM (BB*SS)
#define NBH (BB*HH)
#define KP2 (DD/2)   // 256 packed u32 per row

// Packed bf16x2 split planes (uint32 = 2 bf16 along last dim)
__device__ uint32_t g_Qh[NBH*SS*32], g_Ql[NBH*SS*32];   // [bh][s][d/2], pre-scaled by 0.125*log2e
__device__ uint32_t g_Kh[NBH*SS*32], g_Kl[NBH*SS*32];   // [bh][s][d/2]
__device__ uint32_t g_Vh[NBH*DKK*(SS/2)], g_Vl[NBH*DKK*(SS/2)]; // [bh][d][s/2] (transposed)
__device__ uint32_t g_Ch[MM*KP2], g_Cl[MM*KP2];         // context split [m][k/2]
__device__ uint32_t g_XqH[MM*KP2], g_XqL[MM*KP2];       // presplit inputs
__device__ uint32_t g_XkH[MM*KP2], g_XkL[MM*KP2];
__device__ uint32_t g_XvH[MM*KP2], g_XvL[MM*KP2];
__device__ uint32_t g_WqH[DD*KP2], g_WqL[DD*KP2];       // presplit weights
__device__ uint32_t g_WkH[DD*KP2], g_WkL[DD*KP2];
__device__ uint32_t g_WvH[DD*KP2], g_WvL[DD*KP2];
__device__ uint32_t g_WoH[DD*KP2], g_WoL[DD*KP2];

// ---------------------------------------------------------------------------
__device__ __forceinline__ void mma_bf16(float* c, const uint32_t* a, const uint32_t* b) {
    asm volatile(
        "mma.sync.aligned.m16n8k16.row.col.f32.bf16.bf16.f32 "
        "{%0,%1,%2,%3}, {%4,%5,%6,%7}, {%8,%9}, {%0,%1,%2,%3};"
        : "+f"(c[0]), "+f"(c[1]), "+f"(c[2]), "+f"(c[3])
        : "r"(a[0]), "r"(a[1]), "r"(a[2]), "r"(a[3]), "r"(b[0]), "r"(b[1]));
}
__device__ __forceinline__ void pack_split(float x0, float x1, uint32_t& H, uint32_t& L) {
    uint32_t h;
    asm("cvt.rn.bf16x2.f32 %0, %1, %2;" : "=r"(h) : "f"(x1), "f"(x0));
    float h0 = __uint_as_float(h << 16);
    float h1 = __uint_as_float(h & 0xffff0000u);
    float r0 = x0 - h0, r1 = x1 - h1;
    uint32_t l;
    asm("cvt.rn.bf16x2.f32 %0, %1, %2;" : "=r"(l) : "f"(r1), "f"(r0));
    H = h; L = l;
}
__device__ __forceinline__ uint32_t smem_u32(const void* p) {
    uint32_t a;
    asm("{ .reg .u64 t; cvta.to.shared.u64 t, %1; cvt.u32.u64 %0, t; }" : "=r"(a) : "l"(p));
    return a;
}
__device__ __forceinline__ void ldsm4(uint32_t* r, uint32_t saddr) {
    asm volatile("ldmatrix.sync.aligned.m8n8.x4.shared.b16 {%0,%1,%2,%3}, [%4];"
        : "=r"(r[0]), "=r"(r[1]), "=r"(r[2]), "=r"(r[3]) : "r"(saddr));
}
__device__ __forceinline__ void cp16(uint32_t daddr, const void* gsrc) {
    asm volatile("cp.async.cg.shared.global [%0], [%1], 16;" :: "r"(daddr), "l"(gsrc));
}
#define CP_COMMIT() asm volatile("cp.async.commit_group;" ::: "memory")
#define CP_WAIT0()  asm volatile("cp.async.wait_group 0;" ::: "memory")
#define CP_WAIT1()  asm volatile("cp.async.wait_group 1;" ::: "memory")

// ---------------------------------------------------------------------------
// presplit_all: one launch splits all 7 tensors (grid.y selects tensor).
// y 0..2 : Xq,Xk,Xv (n4 = MM*DD/4 = 1048576 -> 4096 blocks of 256)
// y 3..6 : Wq,Wk,Wv,Wo (n4 = DD*DD/4 = 65536 -> first 256 blocks active)
// ---------------------------------------------------------------------------
__global__ void presplit_all(const float4* Xq, const float4* Xk, const float4* Xv,
                             const float4* Wq, const float4* Wk, const float4* Wv,
                             const float4* Wo)
{
    const int y = blockIdx.y;
    const float4* src;
    uint32_t *H, *L;
    int n4;
    switch (y) {
        case 0: src = Xq; H = g_XqH; L = g_XqL; n4 = MM*DD/4; break;
        case 1: src = Xk; H = g_XkH; L = g_XkL; n4 = MM*DD/4; break;
        case 2: src = Xv; H = g_XvH; L = g_XvL; n4 = MM*DD/4; break;
        case 3: src = Wq; H = g_WqH; L = g_WqL; n4 = DD*DD/4; break;
        case 4: src = Wk; H = g_WkH; L = g_WkL; n4 = DD*DD/4; break;
        case 5: src = Wv; H = g_WvH; L = g_WvL; n4 = DD*DD/4; break;
        default: src = Wo; H = g_WoH; L = g_WoL; n4 = DD*DD/4; break;
    }
    int i = blockIdx.x * blockDim.x + threadIdx.x;
    if (i < n4) {
        float4 v = src[i];
        uint32_t h0, l0, h1, l1;
        pack_split(v.x, v.y, h0, l0);
        pack_split(v.z, v.w, h1, l1);
        *(uint2*)&H[2*i] = make_uint2(h0, h1);
        *(uint2*)&L[2*i] = make_uint2(l0, l1);
    }
}

// ---------------------------------------------------------------------------
// bf16-split GEMM (NT) from presplit planes, cp.async 2-stage pipeline.
// C[m,n] = sum_k A[m,k]*W[n,k] in split-bf16 (3 MMA terms).
// which 0 (Q):  A=Xq planes, B=Wq planes -> g_Qh/g_Ql (qscaled)
// which 1 (K):  A=Xk planes, B=Wk planes -> g_Kh/g_Kl
// which 2 (Vt): A=Wv planes, B=Xv planes -> g_Vh/g_Vl (transposed store)
// which 3 (out):A=g_Ch/Cl,   B=Wo planes -> fp32 out
// Occupancy pinned: 2 CTAs/SM; dynamic smem 80KB (2 stages).
// ---------------------------------------------------------------------------
#define ST4 20               // smem row stride in u32 (16 data + 4 pad)
#define GPL (128*ST4)        // u32 per plane
#define GSMEM (2*4*GPL*4)    // 81920 B

__global__ __launch_bounds__(256, 2)
void gemm_mma(const uint32_t* __restrict__ AH, const uint32_t* __restrict__ AL,
              const uint32_t* __restrict__ BH, const uint32_t* __restrict__ BL,
              float* __restrict__ out_direct, int which)
{
    extern __shared__ uint32_t smG[];
    const uint32_t sb = smem_u32(smG);

    const int tid = threadIdx.x;
    const int wid = tid >> 5;
    const int lid = tid & 31;
    const int gID = lid >> 2;
    const int tig = lid & 3;
    const int bm  = blockIdx.x * 128;
    const int bn  = blockIdx.y * 128;
    const int wm  = (wid & 1) * 64;
    const int wn  = (wid >> 1) * 32;

    auto stage_load = [&](int st, int c) {
        #pragma unroll
        for (int q = 0; q < 8; q++) {
            int idx = q * 256 + tid;       // 0..2047 uint4 slots
            int pl  = idx >> 9;            // plane: 0=AH 1=AL 2=BH 3=BL
            int rem = idx & 511;
            int row = rem >> 2;
            int j4  = (rem & 3) << 2;
            const uint32_t* base = (pl == 0) ? AH : (pl == 1) ? AL : (pl == 2) ? BH : BL;
            int grow = ((pl < 2) ? bm : bn) + row;
            cp16(sb + ((st*4 + pl) * GPL + row * ST4 + j4) * 4,
                 base + (size_t)grow * KP2 + c * 16 + j4);
        }
        CP_COMMIT();
    };

    float acc[4][4][4];
    #pragma unroll
    for (int i = 0; i < 4; i++)
        #pragma unroll
        for (int j = 0; j < 4; j++)
            #pragma unroll
            for (int t = 0; t < 4; t++) acc[i][j][t] = 0.f;

    stage_load(0, 0);

    for (int c = 0; c < DD/32; c++) {
        const int cur = c & 1;
        if (c + 1 < DD/32) { stage_load(cur ^ 1, c + 1); CP_WAIT1(); }
        else               { CP_WAIT0(); }
        __syncthreads();   // stage(c) visible to all

        const uint32_t* Ahi = smG + (cur*4 + 0) * GPL;
        const uint32_t* Alo = smG + (cur*4 + 1) * GPL;
        const uint32_t* Bhi = smG + (cur*4 + 2) * GPL;
        const uint32_t* Blo = smG + (cur*4 + 3) * GPL;

        #pragma unroll
        for (int ks = 0; ks < 2; ks++) {
            const int kp = 8*ks + tig;
            uint32_t bhf[4][2], blf[4][2];
            #pragma unroll
            for (int ni = 0; ni < 4; ni++) {
                int n = wn + ni*8 + gID;
                bhf[ni][0] = Bhi[n*ST4 + kp];  bhf[ni][1] = Bhi[n*ST4 + kp + 4];
                blf[ni][0] = Blo[n*ST4 + kp];  blf[ni][1] = Blo[n*ST4 + kp + 4];
            }
            #pragma unroll
            for (int mi = 0; mi < 4; mi++) {
                int m = wm + mi*16 + gID;
                uint32_t ahf[4], alf[4];
                ahf[0] = Ahi[m*ST4 + kp];       ahf[1] = Ahi[(m+8)*ST4 + kp];
                ahf[2] = Ahi[m*ST4 + kp + 4];   ahf[3] = Ahi[(m+8)*ST4 + kp + 4];
                alf[0] = Alo[m*ST4 + kp];       alf[1] = Alo[(m+8)*ST4 + kp];
                alf[2] = Alo[m*ST4 + kp + 4];   alf[3] = Alo[(m+8)*ST4 + kp + 4];
                #pragma unroll
                for (int ni = 0; ni < 4; ni++) {
                    mma_bf16(acc[mi][ni], ahf, bhf[ni]);
                    mma_bf16(acc[mi][ni], ahf, blf[ni]);
                    mma_bf16(acc[mi][ni], alf, bhf[ni]);
                }
            }
        }
        __syncthreads();   // MMA(c) readers done before buffer reuse
    }

    // ---- epilogue ----
    const float qscale = (which == 0) ? 0.125f * 1.4426950408889634f : 1.0f;
    #pragma unroll
    for (int mi = 0; mi < 4; mi++) {
        int rm = bm + wm + mi*16 + gID;
        #pragma unroll
        for (int ni = 0; ni < 4; ni++) {
            int n = bn + wn + ni*8 + 2*tig;
            float* a = acc[mi][ni];
            if (which <= 1) {
                uint32_t* Hp = (which == 0) ? g_Qh : g_Kh;
                uint32_t* Lp = (which == 0) ? g_Ql : g_Kl;
                int h = n >> 6, dp = (n & 63) >> 1;
                uint32_t H, L;
                pack_split(a[0]*qscale, a[1]*qscale, H, L);
                size_t o0 = ((size_t)((rm >> 11)*HH + h)*SS + (rm & (SS-1)))*32 + dp;
                Hp[o0] = H; Lp[o0] = L;
                pack_split(a[2]*qscale, a[3]*qscale, H, L);
                int r1 = rm + 8;
                size_t o1 = ((size_t)((r1 >> 11)*HH + h)*SS + (r1 & (SS-1)))*32 + dp;
                Hp[o1] = H; Lp[o1] = L;
            } else if (which == 2) {
                int h = rm >> 6, dj = rm & 63;
                int b = n >> 11, sl = n & (SS-1);
                uint32_t H, L;
                pack_split(a[0], a[1], H, L);
                size_t o0 = ((size_t)(b*HH + h)*DKK + dj)*(SS/2) + (sl >> 1);
                g_Vh[o0] = H; g_Vl[o0] = L;
                pack_split(a[2], a[3], H, L);
                size_t o1 = ((size_t)(b*HH + h)*DKK + dj + 8)*(SS/2) + (sl >> 1);
                g_Vh[o1] = H; g_Vl[o1] = L;
            } else {
                *(float2*)&out_direct[(size_t)rm*DD + n]     = make_float2(a[0], a[1]);
                *(float2*)&out_direct[(size_t)(rm+8)*DD + n] = make_float2(a[2], a[3]);
            }
        }
    }
}

// ---------------------------------------------------------------------------
// bf16-split flash attention (causal) — R15-exact (ldmatrix + raw exp2,
// 3 CTAs/SM, split-context epilogue).  Stable at ~191 us.
// ---------------------------------------------------------------------------
#define AST 36   // attn smem row stride in uint32 (32 data + 4 pad)

__global__ __launch_bounds__(128, 3)
void attn_mma()
{
    __shared__ uint32_t sKh[64*AST], sKl[64*AST], sVh[64*AST], sVl[64*AST];

    const int tid = threadIdx.x;
    const int w   = tid >> 5;
    const int lid = tid & 31;
    const int gID = lid >> 2;
    const int tig = lid & 3;

    const int qt = (int)gridDim.x - 1 - (int)blockIdx.x;  // long rows first
    const int bh = blockIdx.y;

    const int q0l = w*16 + gID;          // local row (0..63), second row +8
    const int q0  = qt*64 + q0l;

    const int lmat_i   = lid >> 3;
    const int lmat_off = (((lmat_i >> 1)*8 + (lid & 7))*AST + (lmat_i & 1)*4) * 4;
    const uint32_t aKh = smem_u32(sKh) + lmat_off;
    const uint32_t aKl = smem_u32(sKl) + lmat_off;
    const uint32_t aVh = smem_u32(sVh) + lmat_off;
    const uint32_t aVl = smem_u32(sVl) + lmat_off;

    // ---- Q fragments (hi/lo, pre-scaled by 0.125*log2e), resident ----
    uint32_t qh[4][4], ql[4][4];
    {
        const uint32_t* Qhp = g_Qh + ((size_t)bh*SS + q0)*32;
        const uint32_t* Qlp = g_Ql + ((size_t)bh*SS + q0)*32;
        #pragma unroll
        for (int ks = 0; ks < 4; ks++) {
            int p = 8*ks + tig;
            qh[ks][0] = Qhp[p];          qh[ks][1] = Qhp[8*32 + p];
            qh[ks][2] = Qhp[p + 4];      qh[ks][3] = Qhp[8*32 + p + 4];
            ql[ks][0] = Qlp[p];          ql[ks][1] = Qlp[8*32 + p];
            ql[ks][2] = Qlp[p + 4];      ql[ks][3] = Qlp[8*32 + p + 4];
        }
    }

    float l0 = 0.f, l1 = 0.f;            // raw exp2 sums
    float accO[8][4];
    #pragma unroll
    for (int nt = 0; nt < 8; nt++)
        #pragma unroll
        for (int t = 0; t < 4; t++) accO[nt][t] = 0.f;

    for (int kt = 0; kt <= qt; kt++) {
        __syncthreads();
        #pragma unroll
        for (int it = 0; it < 4; it++) {
            int idx = it*128 + tid;
            int r   = idx >> 3;
            int c4  = (idx & 7) << 2;
            size_t ko = ((size_t)bh*SS + kt*64 + r)*32 + c4;
            *(int4*)&sKh[r*AST + c4] = *(const int4*)&g_Kh[ko];
            *(int4*)&sKl[r*AST + c4] = *(const int4*)&g_Kl[ko];
            size_t vo = ((size_t)bh*DKK + r)*(SS/2) + kt*32 + c4;
            *(int4*)&sVh[r*AST + c4] = *(const int4*)&g_Vh[vo];
            *(int4*)&sVl[r*AST + c4] = *(const int4*)&g_Vl[vo];
        }
        __syncthreads();

        // ---- S = Q K^T (3-term split; log2 domain) ----
        float accS[8][4];
        #pragma unroll
        for (int nt = 0; nt < 8; nt++)
            #pragma unroll
            for (int t = 0; t < 4; t++) accS[nt][t] = 0.f;

        #pragma unroll
        for (int ks = 0; ks < 4; ks++) {
            const int co = ks * 32;
            #pragma unroll
            for (int np = 0; np < 4; np++) {
                const int ro = np * (16*AST*4);
                uint32_t kh4[4], kl4[4];
                ldsm4(kh4, aKh + ro + co);
                ldsm4(kl4, aKl + ro + co);
                mma_bf16(accS[2*np  ], qh[ks], kh4 + 0);
                mma_bf16(accS[2*np  ], qh[ks], kl4 + 0);
                mma_bf16(accS[2*np  ], ql[ks], kh4 + 0);
                mma_bf16(accS[2*np+1], qh[ks], kh4 + 2);
                mma_bf16(accS[2*np+1], qh[ks], kl4 + 2);
                mma_bf16(accS[2*np+1], ql[ks], kh4 + 2);
            }
        }

        // ---- causal mask (diagonal tile only) ----
        if (kt == qt) {
            #pragma unroll
            for (int nt = 0; nt < 8; nt++) {
                int c0 = nt*8 + 2*tig;
                if (c0     > q0l)     accS[nt][0] = -1e30f;
                if (c0 + 1 > q0l)     accS[nt][1] = -1e30f;
                if (c0     > q0l + 8) accS[nt][2] = -1e30f;
                if (c0 + 1 > q0l + 8) accS[nt][3] = -1e30f;
            }
        }

        // ---- raw exp2 softmax numerator ----
        float sum0 = 0.f, sum1 = 0.f;
        #pragma unroll
        for (int nt = 0; nt < 8; nt++) {
            accS[nt][0] = exp2f(accS[nt][0]);
            accS[nt][1] = exp2f(accS[nt][1]);
            accS[nt][2] = exp2f(accS[nt][2]);
            accS[nt][3] = exp2f(accS[nt][3]);
            sum0 += accS[nt][0] + accS[nt][1];
            sum1 += accS[nt][2] + accS[nt][3];
        }
        #pragma unroll
        for (int off = 1; off <= 2; off <<= 1) {
            sum0 += __shfl_xor_sync(0xffffffffu, sum0, off);
            sum1 += __shfl_xor_sync(0xffffffffu, sum1, off);
        }
        l0 += sum0;
        l1 += sum1;

        // ---- P -> bf16 split A-fragments ----
        uint32_t ph[4][4], pl_[4][4];
        #pragma unroll
        for (int ks = 0; ks < 4; ks++) {
            pack_split(accS[2*ks  ][0], accS[2*ks  ][1], ph[ks][0], pl_[ks][0]);
            pack_split(accS[2*ks  ][2], accS[2*ks  ][3], ph[ks][1], pl_[ks][1]);
            pack_split(accS[2*ks+1][0], accS[2*ks+1][1], ph[ks][2], pl_[ks][2]);
            pack_split(accS[2*ks+1][2], accS[2*ks+1][3], ph[ks][3], pl_[ks][3]);
        }

        // ---- O += P V (3-term split) ----
        #pragma unroll
        for (int ks = 0; ks < 4; ks++) {
            const int co = ks * 32;
            #pragma unroll
            for (int np = 0; np < 4; np++) {
                const int ro = np * (16*AST*4);
                uint32_t vh4[4], vl4[4];
                ldsm4(vh4, aVh + ro + co);
                ldsm4(vl4, aVl + ro + co);
                mma_bf16(accO[2*np  ], ph[ks], vh4 + 0);
                mma_bf16(accO[2*np  ], ph[ks], vl4 + 0);
                mma_bf16(accO[2*np  ], pl_[ks], vh4 + 0);
                mma_bf16(accO[2*np+1], ph[ks], vh4 + 2);
                mma_bf16(accO[2*np+1], ph[ks], vl4 + 2);
                mma_bf16(accO[2*np+1], pl_[ks], vh4 + 2);
            }
        }
    }

    // ---- epilogue: split context planes [m][k/2] ----
    const int b = bh >> 3, h = bh & 7;
    const float inv0 = 1.f / l0, inv1 = 1.f / l1;
    const size_t m0r = (size_t)b*SS + q0;
    #pragma unroll
    for (int nt = 0; nt < 8; nt++) {
        int dp = h*32 + nt*4 + tig;
        uint32_t H, L;
        pack_split(accO[nt][0]*inv0, accO[nt][1]*inv0, H, L);
        g_Ch[m0r*KP2 + dp] = H;  g_Cl[m0r*KP2 + dp] = L;
        pack_split(accO[nt][2]*inv1, accO[nt][3]*inv1, H, L);
        g_Ch[(m0r + 8)*KP2 + dp] = H;  g_Cl[(m0r + 8)*KP2 + dp] = L;
    }
}

// ---------------------------------------------------------------------------
extern "C" void kernel_launch(void* const* d_in, const int* in_sizes, int n_in,
                              void* d_out, int out_size)
{
    const float* Xq = (const float*)d_in[0];
    const float* Xk = (const float*)d_in[1];
    const float* Xv = (const float*)d_in[2];
    const float* Wq = (const float*)d_in[3];
    const float* Wk = (const float*)d_in[4];
    const float* Wv = (const float*)d_in[5];
    const float* Wo = (const float*)d_in[6];
    float* out = (float*)d_out;

    static cudaStream_t s1 = nullptr, s2 = nullptr;
    static cudaEvent_t ev0 = nullptr, ev1 = nullptr, ev2 = nullptr;
    if (s1 == nullptr) {
        cudaStreamCreateWithFlags(&s1, cudaStreamNonBlocking);
        cudaStreamCreateWithFlags(&s2, cudaStreamNonBlocking);
        cudaEventCreateWithFlags(&ev0, cudaEventDisableTiming);
        cudaEventCreateWithFlags(&ev1, cudaEventDisableTiming);
        cudaEventCreateWithFlags(&ev2, cudaEventDisableTiming);
        cudaFuncSetAttribute(gemm_mma, cudaFuncAttributeMaxDynamicSharedMemorySize, GSMEM);
    }

    uint32_t *pXqH, *pXqL, *pXkH, *pXkL, *pXvH, *pXvL;
    uint32_t *pWqH, *pWqL, *pWkH, *pWkL, *pWvH, *pWvL, *pWoH, *pWoL, *pCh, *pCl;
    cudaGetSymbolAddress((void**)&pXqH, g_XqH); cudaGetSymbolAddress((void**)&pXqL, g_XqL);
    cudaGetSymbolAddress((void**)&pXkH, g_XkH); cudaGetSymbolAddress((void**)&pXkL, g_XkL);
    cudaGetSymbolAddress((void**)&pXvH, g_XvH); cudaGetSymbolAddress((void**)&pXvL, g_XvL);
    cudaGetSymbolAddress((void**)&pWqH, g_WqH); cudaGetSymbolAddress((void**)&pWqL, g_WqL);
    cudaGetSymbolAddress((void**)&pWkH, g_WkH); cudaGetSymbolAddress((void**)&pWkL, g_WkL);
    cudaGetSymbolAddress((void**)&pWvH, g_WvH); cudaGetSymbolAddress((void**)&pWvL, g_WvL);
    cudaGetSymbolAddress((void**)&pWoH, g_WoH); cudaGetSymbolAddress((void**)&pWoL, g_WoL);
    cudaGetSymbolAddress((void**)&pCh,  g_Ch);  cudaGetSymbolAddress((void**)&pCl,  g_Cl);

    // 1) one batched presplit launch (X rows: 4096 blocks; W rows exit early)
    presplit_all<<<dim3(MM*DD/4/256, 7), 256>>>(
        (const float4*)Xq, (const float4*)Xk, (const float4*)Xv,
        (const float4*)Wq, (const float4*)Wk, (const float4*)Wv, (const float4*)Wo);

    dim3 gqk(MM/128, DD/128);     // 64 x 4

    // 2) fork: Q on capture stream, K on s1, Vt on s2
    cudaEventRecord(ev0, 0);
    cudaStreamWaitEvent(s1, ev0, 0);
    cudaStreamWaitEvent(s2, ev0, 0);
    gemm_mma<<<gqk, 256, GSMEM, 0 >>>(pXqH, pXqL, pWqH, pWqL, nullptr, 0);
    gemm_mma<<<gqk, 256, GSMEM, s1>>>(pXkH, pXkL, pWkH, pWkL, nullptr, 1);
    gemm_mma<<<dim3(DD/128, MM/128), 256, GSMEM, s2>>>(pWvH, pWvL, pXvH, pXvL, nullptr, 2);
    cudaEventRecord(ev1, s1);
    cudaEventRecord(ev2, s2);
    cudaStreamWaitEvent(0, ev1, 0);
    cudaStreamWaitEvent(0, ev2, 0);

    // 3) attention
    attn_mma<<<dim3(SS/64, NBH), 128>>>();

    // 4) output projection (launch #6 -> profiled by ncu -s 5)
    gemm_mma<<<gqk, 256, GSMEM>>>(pCh, pCl, pWoH, pWoL, out, 3);
}

// round 17
// speedup vs baseline: 1.0108x; 1.0108x over previous
#include <cuda_runtime.h>
#include <cstdint>

#define BB 4
#define SS 2048
#define DD 512
#define HH 8
#define DKK 64
#define MM (BB*SS)
#define NBH (BB*HH)
#define KP2 (DD/2)   // 256 packed u32 per row

// Packed bf16x2 split planes (uint32 = 2 bf16 along last dim)
__device__ uint32_t g_Qh[NBH*SS*32], g_Ql[NBH*SS*32];   // [bh][s][d/2], pre-scaled by 0.125*log2e
__device__ uint32_t g_Kh[NBH*SS*32], g_Kl[NBH*SS*32];   // [bh][s][d/2]
__device__ uint32_t g_Vh[NBH*DKK*(SS/2)], g_Vl[NBH*DKK*(SS/2)]; // [bh][d][s/2] (transposed)
__device__ uint32_t g_Ch[MM*KP2], g_Cl[MM*KP2];         // context split [m][k/2]
__device__ uint32_t g_XqH[MM*KP2], g_XqL[MM*KP2];       // presplit inputs
__device__ uint32_t g_XkH[MM*KP2], g_XkL[MM*KP2];
__device__ uint32_t g_XvH[MM*KP2], g_XvL[MM*KP2];
__device__ uint32_t g_WqH[DD*KP2], g_WqL[DD*KP2];       // presplit weights
__device__ uint32_t g_WkH[DD*KP2], g_WkL[DD*KP2];
__device__ uint32_t g_WvH[DD*KP2], g_WvL[DD*KP2];
__device__ uint32_t g_WoH[DD*KP2], g_WoL[DD*KP2];

// ---------------------------------------------------------------------------
__device__ __forceinline__ void mma_bf16(float* c, const uint32_t* a, const uint32_t* b) {
    asm volatile(
        "mma.sync.aligned.m16n8k16.row.col.f32.bf16.bf16.f32 "
        "{%0,%1,%2,%3}, {%4,%5,%6,%7}, {%8,%9}, {%0,%1,%2,%3};"
        : "+f"(c[0]), "+f"(c[1]), "+f"(c[2]), "+f"(c[3])
        : "r"(a[0]), "r"(a[1]), "r"(a[2]), "r"(a[3]), "r"(b[0]), "r"(b[1]));
}
__device__ __forceinline__ void pack_split(float x0, float x1, uint32_t& H, uint32_t& L) {
    uint32_t h;
    asm("cvt.rn.bf16x2.f32 %0, %1, %2;" : "=r"(h) : "f"(x1), "f"(x0));
    float h0 = __uint_as_float(h << 16);
    float h1 = __uint_as_float(h & 0xffff0000u);
    float r0 = x0 - h0, r1 = x1 - h1;
    uint32_t l;
    asm("cvt.rn.bf16x2.f32 %0, %1, %2;" : "=r"(l) : "f"(r1), "f"(r0));
    H = h; L = l;
}
__device__ __forceinline__ uint32_t smem_u32(const void* p) {
    uint32_t a;
    asm("{ .reg .u64 t; cvta.to.shared.u64 t, %1; cvt.u32.u64 %0, t; }" : "=r"(a) : "l"(p));
    return a;
}
__device__ __forceinline__ void ldsm4(uint32_t* r, uint32_t saddr) {
    asm volatile("ldmatrix.sync.aligned.m8n8.x4.shared.b16 {%0,%1,%2,%3}, [%4];"
        : "=r"(r[0]), "=r"(r[1]), "=r"(r[2]), "=r"(r[3]) : "r"(saddr));
}
__device__ __forceinline__ void cp16(uint32_t daddr, const void* gsrc) {
    asm volatile("cp.async.cg.shared.global [%0], [%1], 16;" :: "r"(daddr), "l"(gsrc));
}
#define CP_COMMIT() asm volatile("cp.async.commit_group;" ::: "memory")
#define CP_WAIT0()  asm volatile("cp.async.wait_group 0;" ::: "memory")
#define CP_WAIT1()  asm volatile("cp.async.wait_group 1;" ::: "memory")

// ---------------------------------------------------------------------------
// presplit_all: one launch splits all 7 tensors (grid.y selects tensor).
// ---------------------------------------------------------------------------
__global__ void presplit_all(const float4* Xq, const float4* Xk, const float4* Xv,
                             const float4* Wq, const float4* Wk, const float4* Wv,
                             const float4* Wo)
{
    const int y = blockIdx.y;
    const float4* src;
    uint32_t *H, *L;
    int n4;
    switch (y) {
        case 0: src = Xq; H = g_XqH; L = g_XqL; n4 = MM*DD/4; break;
        case 1: src = Xk; H = g_XkH; L = g_XkL; n4 = MM*DD/4; break;
        case 2: src = Xv; H = g_XvH; L = g_XvL; n4 = MM*DD/4; break;
        case 3: src = Wq; H = g_WqH; L = g_WqL; n4 = DD*DD/4; break;
        case 4: src = Wk; H = g_WkH; L = g_WkL; n4 = DD*DD/4; break;
        case 5: src = Wv; H = g_WvH; L = g_WvL; n4 = DD*DD/4; break;
        default: src = Wo; H = g_WoH; L = g_WoL; n4 = DD*DD/4; break;
    }
    int i = blockIdx.x * blockDim.x + threadIdx.x;
    if (i < n4) {
        float4 v = src[i];
        uint32_t h0, l0, h1, l1;
        pack_split(v.x, v.y, h0, l0);
        pack_split(v.z, v.w, h1, l1);
        *(uint2*)&H[2*i] = make_uint2(h0, h1);
        *(uint2*)&L[2*i] = make_uint2(l0, l1);
    }
}

// ---------------------------------------------------------------------------
// bf16-split GEMM (NT) from presplit planes, cp.async 2-stage pipeline.
// TERM-OUTER MMA ORDER: same-accumulator reuse distance 1 -> 4.
// Occupancy pinned: 2 CTAs/SM; dynamic smem 80KB.
// ---------------------------------------------------------------------------
#define ST4 20               // smem row stride in u32 (16 data + 4 pad)
#define GPL (128*ST4)        // u32 per plane
#define GSMEM (2*4*GPL*4)    // 81920 B

__global__ __launch_bounds__(256, 2)
void gemm_mma(const uint32_t* __restrict__ AH, const uint32_t* __restrict__ AL,
              const uint32_t* __restrict__ BH, const uint32_t* __restrict__ BL,
              float* __restrict__ out_direct, int which)
{
    extern __shared__ uint32_t smG[];
    const uint32_t sb = smem_u32(smG);

    const int tid = threadIdx.x;
    const int wid = tid >> 5;
    const int lid = tid & 31;
    const int gID = lid >> 2;
    const int tig = lid & 3;
    const int bm  = blockIdx.x * 128;
    const int bn  = blockIdx.y * 128;
    const int wm  = (wid & 1) * 64;
    const int wn  = (wid >> 1) * 32;

    auto stage_load = [&](int st, int c) {
        #pragma unroll
        for (int q = 0; q < 8; q++) {
            int idx = q * 256 + tid;
            int pl  = idx >> 9;
            int rem = idx & 511;
            int row = rem >> 2;
            int j4  = (rem & 3) << 2;
            const uint32_t* base = (pl == 0) ? AH : (pl == 1) ? AL : (pl == 2) ? BH : BL;
            int grow = ((pl < 2) ? bm : bn) + row;
            cp16(sb + ((st*4 + pl) * GPL + row * ST4 + j4) * 4,
                 base + (size_t)grow * KP2 + c * 16 + j4);
        }
        CP_COMMIT();
    };

    float acc[4][4][4];
    #pragma unroll
    for (int i = 0; i < 4; i++)
        #pragma unroll
        for (int j = 0; j < 4; j++)
            #pragma unroll
            for (int t = 0; t < 4; t++) acc[i][j][t] = 0.f;

    stage_load(0, 0);

    for (int c = 0; c < DD/32; c++) {
        const int cur = c & 1;
        if (c + 1 < DD/32) { stage_load(cur ^ 1, c + 1); CP_WAIT1(); }
        else               { CP_WAIT0(); }
        __syncthreads();

        const uint32_t* Ahi = smG + (cur*4 + 0) * GPL;
        const uint32_t* Alo = smG + (cur*4 + 1) * GPL;
        const uint32_t* Bhi = smG + (cur*4 + 2) * GPL;
        const uint32_t* Blo = smG + (cur*4 + 3) * GPL;

        #pragma unroll
        for (int ks = 0; ks < 2; ks++) {
            const int kp = 8*ks + tig;
            uint32_t bhf[4][2], blf[4][2];
            #pragma unroll
            for (int ni = 0; ni < 4; ni++) {
                int n = wn + ni*8 + gID;
                bhf[ni][0] = Bhi[n*ST4 + kp];  bhf[ni][1] = Bhi[n*ST4 + kp + 4];
                blf[ni][0] = Blo[n*ST4 + kp];  blf[ni][1] = Blo[n*ST4 + kp + 4];
            }
            #pragma unroll
            for (int mi = 0; mi < 4; mi++) {
                int m = wm + mi*16 + gID;
                uint32_t ahf[4], alf[4];
                ahf[0] = Ahi[m*ST4 + kp];       ahf[1] = Ahi[(m+8)*ST4 + kp];
                ahf[2] = Ahi[m*ST4 + kp + 4];   ahf[3] = Ahi[(m+8)*ST4 + kp + 4];
                alf[0] = Alo[m*ST4 + kp];       alf[1] = Alo[(m+8)*ST4 + kp];
                alf[2] = Alo[m*ST4 + kp + 4];   alf[3] = Alo[(m+8)*ST4 + kp + 4];
                // term-outer: 4 independent accumulators between same-acc reuses
                #pragma unroll
                for (int ni = 0; ni < 4; ni++) mma_bf16(acc[mi][ni], ahf, bhf[ni]);
                #pragma unroll
                for (int ni = 0; ni < 4; ni++) mma_bf16(acc[mi][ni], ahf, blf[ni]);
                #pragma unroll
                for (int ni = 0; ni < 4; ni++) mma_bf16(acc[mi][ni], alf, bhf[ni]);
            }
        }
        __syncthreads();
    }

    // ---- epilogue ----
    const float qscale = (which == 0) ? 0.125f * 1.4426950408889634f : 1.0f;
    #pragma unroll
    for (int mi = 0; mi < 4; mi++) {
        int rm = bm + wm + mi*16 + gID;
        #pragma unroll
        for (int ni = 0; ni < 4; ni++) {
            int n = bn + wn + ni*8 + 2*tig;
            float* a = acc[mi][ni];
            if (which <= 1) {
                uint32_t* Hp = (which == 0) ? g_Qh : g_Kh;
                uint32_t* Lp = (which == 0) ? g_Ql : g_Kl;
                int h = n >> 6, dp = (n & 63) >> 1;
                uint32_t H, L;
                pack_split(a[0]*qscale, a[1]*qscale, H, L);
                size_t o0 = ((size_t)((rm >> 11)*HH + h)*SS + (rm & (SS-1)))*32 + dp;
                Hp[o0] = H; Lp[o0] = L;
                pack_split(a[2]*qscale, a[3]*qscale, H, L);
                int r1 = rm + 8;
                size_t o1 = ((size_t)((r1 >> 11)*HH + h)*SS + (r1 & (SS-1)))*32 + dp;
                Hp[o1] = H; Lp[o1] = L;
            } else if (which == 2) {
                int h = rm >> 6, dj = rm & 63;
                int b = n >> 11, sl = n & (SS-1);
                uint32_t H, L;
                pack_split(a[0], a[1], H, L);
                size_t o0 = ((size_t)(b*HH + h)*DKK + dj)*(SS/2) + (sl >> 1);
                g_Vh[o0] = H; g_Vl[o0] = L;
                pack_split(a[2], a[3], H, L);
                size_t o1 = ((size_t)(b*HH + h)*DKK + dj + 8)*(SS/2) + (sl >> 1);
                g_Vh[o1] = H; g_Vl[o1] = L;
            } else {
                *(float2*)&out_direct[(size_t)rm*DD + n]     = make_float2(a[0], a[1]);
                *(float2*)&out_direct[(size_t)(rm+8)*DD + n] = make_float2(a[2], a[3]);
            }
        }
    }
}

// ---------------------------------------------------------------------------
// bf16-split flash attention (causal) — R16 body with acc-tile INTERLEAVED
// MMA order in QK and PV (same-acc distance 1 -> 2).  3 CTAs/SM pinned.
// ---------------------------------------------------------------------------
#define AST 36   // attn smem row stride in uint32 (32 data + 4 pad)

__global__ __launch_bounds__(128, 3)
void attn_mma()
{
    __shared__ uint32_t sKh[64*AST], sKl[64*AST], sVh[64*AST], sVl[64*AST];

    const int tid = threadIdx.x;
    const int w   = tid >> 5;
    const int lid = tid & 31;
    const int gID = lid >> 2;
    const int tig = lid & 3;

    const int qt = (int)gridDim.x - 1 - (int)blockIdx.x;  // long rows first
    const int bh = blockIdx.y;

    const int q0l = w*16 + gID;          // local row (0..63), second row +8
    const int q0  = qt*64 + q0l;

    const int lmat_i   = lid >> 3;
    const int lmat_off = (((lmat_i >> 1)*8 + (lid & 7))*AST + (lmat_i & 1)*4) * 4;
    const uint32_t aKh = smem_u32(sKh) + lmat_off;
    const uint32_t aKl = smem_u32(sKl) + lmat_off;
    const uint32_t aVh = smem_u32(sVh) + lmat_off;
    const uint32_t aVl = smem_u32(sVl) + lmat_off;

    // ---- Q fragments (hi/lo, pre-scaled by 0.125*log2e), resident ----
    uint32_t qh[4][4], ql[4][4];
    {
        const uint32_t* Qhp = g_Qh + ((size_t)bh*SS + q0)*32;
        const uint32_t* Qlp = g_Ql + ((size_t)bh*SS + q0)*32;
        #pragma unroll
        for (int ks = 0; ks < 4; ks++) {
            int p = 8*ks + tig;
            qh[ks][0] = Qhp[p];          qh[ks][1] = Qhp[8*32 + p];
            qh[ks][2] = Qhp[p + 4];      qh[ks][3] = Qhp[8*32 + p + 4];
            ql[ks][0] = Qlp[p];          ql[ks][1] = Qlp[8*32 + p];
            ql[ks][2] = Qlp[p + 4];      ql[ks][3] = Qlp[8*32 + p + 4];
        }
    }

    float l0 = 0.f, l1 = 0.f;            // raw exp2 sums
    float accO[8][4];
    #pragma unroll
    for (int nt = 0; nt < 8; nt++)
        #pragma unroll
        for (int t = 0; t < 4; t++) accO[nt][t] = 0.f;

    for (int kt = 0; kt <= qt; kt++) {
        __syncthreads();
        #pragma unroll
        for (int it = 0; it < 4; it++) {
            int idx = it*128 + tid;
            int r   = idx >> 3;
            int c4  = (idx & 7) << 2;
            size_t ko = ((size_t)bh*SS + kt*64 + r)*32 + c4;
            *(int4*)&sKh[r*AST + c4] = *(const int4*)&g_Kh[ko];
            *(int4*)&sKl[r*AST + c4] = *(const int4*)&g_Kl[ko];
            size_t vo = ((size_t)bh*DKK + r)*(SS/2) + kt*32 + c4;
            *(int4*)&sVh[r*AST + c4] = *(const int4*)&g_Vh[vo];
            *(int4*)&sVl[r*AST + c4] = *(const int4*)&g_Vl[vo];
        }
        __syncthreads();

        // ---- S = Q K^T (3-term split; interleaved acc order) ----
        float accS[8][4];
        #pragma unroll
        for (int nt = 0; nt < 8; nt++)
            #pragma unroll
            for (int t = 0; t < 4; t++) accS[nt][t] = 0.f;

        #pragma unroll
        for (int ks = 0; ks < 4; ks++) {
            const int co = ks * 32;
            #pragma unroll
            for (int np = 0; np < 4; np++) {
                const int ro = np * (16*AST*4);
                uint32_t kh4[4], kl4[4];
                ldsm4(kh4, aKh + ro + co);
                ldsm4(kl4, aKl + ro + co);
                // interleave the two acc tiles: same-acc distance 2
                mma_bf16(accS[2*np  ], qh[ks], kh4 + 0);
                mma_bf16(accS[2*np+1], qh[ks], kh4 + 2);
                mma_bf16(accS[2*np  ], qh[ks], kl4 + 0);
                mma_bf16(accS[2*np+1], qh[ks], kl4 + 2);
                mma_bf16(accS[2*np  ], ql[ks], kh4 + 0);
                mma_bf16(accS[2*np+1], ql[ks], kh4 + 2);
            }
        }

        // ---- causal mask (diagonal tile only) ----
        if (kt == qt) {
            #pragma unroll
            for (int nt = 0; nt < 8; nt++) {
                int c0 = nt*8 + 2*tig;
                if (c0     > q0l)     accS[nt][0] = -1e30f;
                if (c0 + 1 > q0l)     accS[nt][1] = -1e30f;
                if (c0     > q0l + 8) accS[nt][2] = -1e30f;
                if (c0 + 1 > q0l + 8) accS[nt][3] = -1e30f;
            }
        }

        // ---- raw exp2 softmax numerator ----
        float sum0 = 0.f, sum1 = 0.f;
        #pragma unroll
        for (int nt = 0; nt < 8; nt++) {
            accS[nt][0] = exp2f(accS[nt][0]);
            accS[nt][1] = exp2f(accS[nt][1]);
            accS[nt][2] = exp2f(accS[nt][2]);
            accS[nt][3] = exp2f(accS[nt][3]);
            sum0 += accS[nt][0] + accS[nt][1];
            sum1 += accS[nt][2] + accS[nt][3];
        }
        #pragma unroll
        for (int off = 1; off <= 2; off <<= 1) {
            sum0 += __shfl_xor_sync(0xffffffffu, sum0, off);
            sum1 += __shfl_xor_sync(0xffffffffu, sum1, off);
        }
        l0 += sum0;
        l1 += sum1;

        // ---- P -> bf16 split A-fragments ----
        uint32_t ph[4][4], pl_[4][4];
        #pragma unroll
        for (int ks = 0; ks < 4; ks++) {
            pack_split(accS[2*ks  ][0], accS[2*ks  ][1], ph[ks][0], pl_[ks][0]);
            pack_split(accS[2*ks  ][2], accS[2*ks  ][3], ph[ks][1], pl_[ks][1]);
            pack_split(accS[2*ks+1][0], accS[2*ks+1][1], ph[ks][2], pl_[ks][2]);
            pack_split(accS[2*ks+1][2], accS[2*ks+1][3], ph[ks][3], pl_[ks][3]);
        }

        // ---- O += P V (3-term split; interleaved acc order) ----
        #pragma unroll
        for (int ks = 0; ks < 4; ks++) {
            const int co = ks * 32;
            #pragma unroll
            for (int np = 0; np < 4; np++) {
                const int ro = np * (16*AST*4);
                uint32_t vh4[4], vl4[4];
                ldsm4(vh4, aVh + ro + co);
                ldsm4(vl4, aVl + ro + co);
                mma_bf16(accO[2*np  ], ph[ks], vh4 + 0);
                mma_bf16(accO[2*np+1], ph[ks], vh4 + 2);
                mma_bf16(accO[2*np  ], ph[ks], vl4 + 0);
                mma_bf16(accO[2*np+1], ph[ks], vl4 + 2);
                mma_bf16(accO[2*np  ], pl_[ks], vh4 + 0);
                mma_bf16(accO[2*np+1], pl_[ks], vh4 + 2);
            }
        }
    }

    // ---- epilogue: split context planes [m][k/2] ----
    const int b = bh >> 3, h = bh & 7;
    const float inv0 = 1.f / l0, inv1 = 1.f / l1;
    const size_t m0r = (size_t)b*SS + q0;
    #pragma unroll
    for (int nt = 0; nt < 8; nt++) {
        int dp = h*32 + nt*4 + tig;
        uint32_t H, L;
        pack_split(accO[nt][0]*inv0, accO[nt][1]*inv0, H, L);
        g_Ch[m0r*KP2 + dp] = H;  g_Cl[m0r*KP2 + dp] = L;
        pack_split(accO[nt][2]*inv1, accO[nt][3]*inv1, H, L);
        g_Ch[(m0r + 8)*KP2 + dp] = H;  g_Cl[(m0r + 8)*KP2 + dp] = L;
    }
}

// ---------------------------------------------------------------------------
extern "C" void kernel_launch(void* const* d_in, const int* in_sizes, int n_in,
                              void* d_out, int out_size)
{
    const float* Xq = (const float*)d_in[0];
    const float* Xk = (const float*)d_in[1];
    const float* Xv = (const float*)d_in[2];
    const float* Wq = (const float*)d_in[3];
    const float* Wk = (const float*)d_in[4];
    const float* Wv = (const float*)d_in[5];
    const float* Wo = (const float*)d_in[6];
    float* out = (float*)d_out;

    static cudaStream_t s1 = nullptr, s2 = nullptr;
    static cudaEvent_t ev0 = nullptr, ev1 = nullptr, ev2 = nullptr;
    if (s1 == nullptr) {
        cudaStreamCreateWithFlags(&s1, cudaStreamNonBlocking);
        cudaStreamCreateWithFlags(&s2, cudaStreamNonBlocking);
        cudaEventCreateWithFlags(&ev0, cudaEventDisableTiming);
        cudaEventCreateWithFlags(&ev1, cudaEventDisableTiming);
        cudaEventCreateWithFlags(&ev2, cudaEventDisableTiming);
        cudaFuncSetAttribute(gemm_mma, cudaFuncAttributeMaxDynamicSharedMemorySize, GSMEM);
    }

    uint32_t *pXqH, *pXqL, *pXkH, *pXkL, *pXvH, *pXvL;
    uint32_t *pWqH, *pWqL, *pWkH, *pWkL, *pWvH, *pWvL, *pWoH, *pWoL, *pCh, *pCl;
    cudaGetSymbolAddress((void**)&pXqH, g_XqH); cudaGetSymbolAddress((void**)&pXqL, g_XqL);
    cudaGetSymbolAddress((void**)&pXkH, g_XkH); cudaGetSymbolAddress((void**)&pXkL, g_XkL);
    cudaGetSymbolAddress((void**)&pXvH, g_XvH); cudaGetSymbolAddress((void**)&pXvL, g_XvL);
    cudaGetSymbolAddress((void**)&pWqH, g_WqH); cudaGetSymbolAddress((void**)&pWqL, g_WqL);
    cudaGetSymbolAddress((void**)&pWkH, g_WkH); cudaGetSymbolAddress((void**)&pWkL, g_WkL);
    cudaGetSymbolAddress((void**)&pWvH, g_WvH); cudaGetSymbolAddress((void**)&pWvL, g_WvL);
    cudaGetSymbolAddress((void**)&pWoH, g_WoH); cudaGetSymbolAddress((void**)&pWoL, g_WoL);
    cudaGetSymbolAddress((void**)&pCh,  g_Ch);  cudaGetSymbolAddress((void**)&pCl,  g_Cl);

    presplit_all<<<dim3(MM*DD/4/256, 7), 256>>>(
        (const float4*)Xq, (const float4*)Xk, (const float4*)Xv,
        (const float4*)Wq, (const float4*)Wk, (const float4*)Wv, (const float4*)Wo);

    dim3 gqk(MM/128, DD/128);     // 64 x 4

    cudaEventRecord(ev0, 0);
    cudaStreamWaitEvent(s1, ev0, 0);
    cudaStreamWaitEvent(s2, ev0, 0);
    gemm_mma<<<gqk, 256, GSMEM, 0 >>>(pXqH, pXqL, pWqH, pWqL, nullptr, 0);
    gemm_mma<<<gqk, 256, GSMEM, s1>>>(pXkH, pXkL, pWkH, pWkL, nullptr, 1);
    gemm_mma<<<dim3(DD/128, MM/128), 256, GSMEM, s2>>>(pWvH, pWvL, pXvH, pXvL, nullptr, 2);
    cudaEventRecord(ev1, s1);
    cudaEventRecord(ev2, s2);
    cudaStreamWaitEvent(0, ev1, 0);
    cudaStreamWaitEvent(0, ev2, 0);

    attn_mma<<<dim3(SS/64, NBH), 128>>>();

    gemm_mma<<<gqk, 256, GSMEM>>>(pCh, pCl, pWoH, pWoL, out, 3);
}